// round 12
// baseline (speedup 1.0000x reference)
#include <cuda_runtime.h>

#define NN 8
#define BB 4
#define CC 32
#define HW 9216
#define PT 32                  // pixels per block tile
#define NTILE (HW / PT)        // 288
#define TOTAL (NN * BB * CC * HW)

typedef unsigned long long ull;

// smem: xs[8*32][32] fl, wd[8*32][32] fl, C2[8*16][32] ull
#define XS_F 8192
#define WD_F 8192
#define C2_U 4096
#define SMEM_BYTES ((XS_F + WD_F) * 4 + C2_U * 8)   // 98304 -> 2 blocks/SM

__device__ float g_buf0[TOTAL];
__device__ float g_buf1[TOTAL];
__device__ float g_wt[NN * 2 * CC * CC];   // [i][{wd,wc}][k][o]

__device__ __forceinline__ ull fma2(ull a, ull b, ull c) {
    ull d;
    asm("fma.rn.f32x2 %0, %1, %2, %3;" : "=l"(d) : "l"(a), "l"(b), "l"(c));
    return d;
}
union U2 { ull u; float2 f; };
__device__ __forceinline__ ull pack2(float lo, float hi) {
    U2 t; t.f.x = lo; t.f.y = hi; return t.u;
}

// ---- prep: [i][o][2C] -> [i][{wd, wc=ws-wd}][k][o] ----
extern "C" __global__ void prep_kernel(const float* __restrict__ W_edge) {
    const int e = blockIdx.x * 256 + threadIdx.x;   // 0..8191
    const int o = e & 31;
    const int k = (e >> 5) & 31;
    const int i = e >> 10;
    const float wd = W_edge[(i * CC + o) * (2 * CC) + k];
    const float ws = W_edge[(i * CC + o) * (2 * CC) + CC + k];
    g_wt[((i * 2 + 0) * CC + k) * CC + o] = wd;
    g_wt[((i * 2 + 1) * CC + k) * CC + o] = ws - wd;
}

// 16 FFMA2 per k: accY[m*4+p] += {w[o0+2m],w[o0+2m+1]} * {x[px0+p],x[px0+p]}
#define K_BODY(WROW, XROW)                                                    \
  _Pragma("unroll")                                                           \
  for (int k = 0; k < 32; ++k) {                                              \
      const ulonglong2 wA = *(const ulonglong2*)((WROW) + k * 32 + o0);       \
      const ulonglong2 wB = *(const ulonglong2*)((WROW) + k * 32 + o0 + 4);   \
      const float4 xv = *(const float4*)((XROW) + k * 32 + px0);              \
      const ull x0 = pack2(xv.x, xv.x);                                       \
      const ull x1 = pack2(xv.y, xv.y);                                       \
      const ull x2 = pack2(xv.z, xv.z);                                       \
      const ull x3 = pack2(xv.w, xv.w);                                       \
      accY[0]  = fma2(wA.x, x0, accY[0]);                                     \
      accY[1]  = fma2(wA.x, x1, accY[1]);                                     \
      accY[2]  = fma2(wA.x, x2, accY[2]);                                     \
      accY[3]  = fma2(wA.x, x3, accY[3]);                                     \
      accY[4]  = fma2(wA.y, x0, accY[4]);                                     \
      accY[5]  = fma2(wA.y, x1, accY[5]);                                     \
      accY[6]  = fma2(wA.y, x2, accY[6]);                                     \
      accY[7]  = fma2(wA.y, x3, accY[7]);                                     \
      accY[8]  = fma2(wB.x, x0, accY[8]);                                     \
      accY[9]  = fma2(wB.x, x1, accY[9]);                                     \
      accY[10] = fma2(wB.x, x2, accY[10]);                                    \
      accY[11] = fma2(wB.x, x3, accY[11]);                                    \
      accY[12] = fma2(wB.y, x0, accY[12]);                                    \
      accY[13] = fma2(wB.y, x1, accY[13]);                                    \
      accY[14] = fma2(wB.y, x2, accY[14]);                                    \
      accY[15] = fma2(wB.y, x3, accY[15]);                                    \
  }

// out[i] = x_i + sum_{j!=i} relu(Wd_i @ x_j + C_i) * x_j
// C_i = (Ws_i - Wd_i) @ x_i + b_i
extern "C" __global__ void __launch_bounds__(256, 2)
step_kernel(const float* __restrict__ in,
            const float* __restrict__ b_edge,   // [8][32]
            float* __restrict__ out)
{
    extern __shared__ float sm[];
    float* xs   = sm;                    // [n*32+k][32 px]  (128B rows)
    float* wd_s = sm + XS_F;             // [i*32+k][32 o]   (128B rows)
    ull*   C2   = (ull*)(sm + XS_F + WD_F);  // [i*16 + m*4+p][lane]

    const int bx    = blockIdx.x;
    const int b     = bx / NTILE;
    const int pbase = (bx % NTILE) * PT;
    const int tid   = threadIdx.x;

    // ---- cooperative loads: xs (8192 fl) + wd_s (8192 fl), float4 coalesced ----
    #pragma unroll
    for (int t = 0; t < 8; ++t) {
        const int e   = tid + t * 256;   // 0..2047 float4 units
        const int row = e >> 3;          // n*32 + k
        const int c4  = e & 7;
        const int n = row >> 5, k = row & 31;
        const float4 v = *reinterpret_cast<const float4*>(
            in + ((n * BB + b) * CC + k) * HW + pbase + c4 * 4);
        *reinterpret_cast<float4*>(xs + row * 32 + c4 * 4) = v;
    }
    #pragma unroll
    for (int t = 0; t < 8; ++t) {
        const int e   = tid + t * 256;
        const int row = e >> 3;          // i*32 + k
        const int c4  = e & 7;
        const int i2 = row >> 5, k = row & 31;
        const float4 v = *reinterpret_cast<const float4*>(
            g_wt + ((i2 * 2 + 0) * CC + k) * CC + c4 * 4);
        *reinterpret_cast<float4*>(wd_s + row * 32 + c4 * 4) = v;
    }
    __syncthreads();   // the only block-wide sync

    const int i    = tid >> 5;           // warp = receiver
    const int lane = tid & 31;
    const int rg   = lane >> 3;          // row-group
    const int pg   = lane & 7;           // px-group
    const int o0   = rg * 8;
    const int px0  = pg * 4;

    const float* wrow_d = wd_s + i * (CC * 32);
    const float* xrow_i = xs + i * (CC * 32);
    ull* C2me = C2 + i * 16 * 32 + lane;

    ull accY[16];
    float accO[8][4];

    // ---- C-GEMM: C_i = Wc_i @ x_i + b_i (wc streamed from L2-resident g_wt) ----
    {
        const float4 bA = *reinterpret_cast<const float4*>(b_edge + i * CC + o0);
        const float4 bB = *reinterpret_cast<const float4*>(b_edge + i * CC + o0 + 4);
        const ull b0 = pack2(bA.x, bA.y), b1 = pack2(bA.z, bA.w);
        const ull b2 = pack2(bB.x, bB.y), b3 = pack2(bB.z, bB.w);
        #pragma unroll
        for (int p = 0; p < 4; ++p) {
            accY[0 + p] = b0; accY[4 + p] = b1;
            accY[8 + p] = b2; accY[12 + p] = b3;
        }
        const float* wrow_c = g_wt + ((i * 2 + 1) * CC) * CC;
        K_BODY(wrow_c, xrow_i)
        // stash C (per-thread private slots; same-thread RAW -> no sync needed)
        #pragma unroll
        for (int q = 0; q < 16; ++q) C2me[q * 32] = accY[q];
    }

    // ---- accO init: residual x_i[o][px] ----
    #pragma unroll
    for (int n = 0; n < 8; ++n) {
        const float4 v = *reinterpret_cast<const float4*>(
            xrow_i + (o0 + n) * 32 + px0);
        accO[n][0] = v.x; accO[n][1] = v.y; accO[n][2] = v.z; accO[n][3] = v.w;
    }

    // ---- j-loop ----
    #pragma unroll 1
    for (int jl = 0; jl < 7; ++jl) {
        const int jj = jl + (jl >= i ? 1 : 0);
        const float* xrow_j = xs + jj * (CC * 32);

        #pragma unroll
        for (int q = 0; q < 16; ++q) accY[q] = C2me[q * 32];

        K_BODY(wrow_d, xrow_j)

        // epilogue: accO += relu(Y) * x_j[o][px]
        #pragma unroll
        for (int m = 0; m < 4; ++m) {
            const float4 xlo = *reinterpret_cast<const float4*>(
                xrow_j + (o0 + 2 * m + 0) * 32 + px0);
            const float4 xhi = *reinterpret_cast<const float4*>(
                xrow_j + (o0 + 2 * m + 1) * 32 + px0);
            const float xl[4] = {xlo.x, xlo.y, xlo.z, xlo.w};
            const float xh[4] = {xhi.x, xhi.y, xhi.z, xhi.w};
            #pragma unroll
            for (int p = 0; p < 4; ++p) {
                U2 y; y.u = accY[m * 4 + p];
                accO[2 * m + 0][p] = fmaf(fmaxf(y.f.x, 0.0f), xl[p], accO[2 * m + 0][p]);
                accO[2 * m + 1][p] = fmaf(fmaxf(y.f.y, 0.0f), xh[p], accO[2 * m + 1][p]);
            }
        }
    }

    // ---- store ----
    #pragma unroll
    for (int n = 0; n < 8; ++n) {
        float4 v;
        v.x = accO[n][0]; v.y = accO[n][1]; v.z = accO[n][2]; v.w = accO[n][3];
        *reinterpret_cast<float4*>(
            out + ((i * BB + b) * CC + (o0 + n)) * HW + pbase + px0) = v;
    }
}

extern "C" void kernel_launch(void* const* d_in, const int* in_sizes, int n_in,
                              void* d_out, int out_size) {
    const float* nodes = (const float*)d_in[0];
    const float* W     = (const float*)d_in[1];
    const float* bvec  = (const float*)d_in[2];
    float* out         = (float*)d_out;

    float *buf0 = nullptr, *buf1 = nullptr;
    cudaGetSymbolAddress((void**)&buf0, g_buf0);
    cudaGetSymbolAddress((void**)&buf1, g_buf1);

    cudaFuncSetAttribute(step_kernel,
                         cudaFuncAttributeMaxDynamicSharedMemorySize, SMEM_BYTES);

    prep_kernel<<<32, 256>>>(W);

    const dim3 grid(BB * NTILE);   // 1152 blocks
    const dim3 block(256);
    step_kernel<<<grid, block, SMEM_BYTES>>>(nodes, bvec, buf0);
    step_kernel<<<grid, block, SMEM_BYTES>>>(buf0,  bvec, buf1);
    step_kernel<<<grid, block, SMEM_BYTES>>>(buf1,  bvec, out);
}

// round 13
// speedup vs baseline: 1.4616x; 1.4616x over previous
#include <cuda_runtime.h>

#define NN 8
#define BB 4
#define CC 32
#define PT 16                    // pixels per block tile
#define HW 9216
#define NTILE (HW / PT)          // 576
#define TOTAL (NN * BB * CC * HW)

#define XDS 36                   // dup row stride (floats): {x,x} pairs + pad
#define XD_F (NN * CC * XDS)     // 9216
#define WD_F (NN * CC * CC)      // 8192
#define XT_F (NN * PT * XDS)     // 4608  (pixel-major transposed copy)
#define SMEM_BYTES ((XD_F + WD_F + XT_F) * 4)   // 88064 -> 2 blocks/SM

typedef unsigned long long ull;

__device__ float g_buf0[TOTAL];
__device__ float g_buf1[TOTAL];
__device__ float g_wt[NN * 2 * CC * CC];   // [i][{wd,wc}][k][o]

__device__ __forceinline__ ull fma2(ull a, ull b, ull c) {
    ull d;
    asm("fma.rn.f32x2 %0, %1, %2, %3;" : "=l"(d) : "l"(a), "l"(b), "l"(c));
    return d;
}
union U2 { ull u; float2 f; };
__device__ __forceinline__ ull pack2(float lo, float hi) {
    U2 t; t.f.x = lo; t.f.y = hi; return t.u;
}

// ---- prep: [i][o][2C] -> [i][{wd, wc=ws-wd}][k][o] ----
extern "C" __global__ void prep_kernel(const float* __restrict__ W_edge) {
    const int e = blockIdx.x * 256 + threadIdx.x;   // 0..8191
    const int o = e & 31;
    const int k = (e >> 5) & 31;
    const int i = e >> 10;
    const float wd = W_edge[(i * CC + o) * (2 * CC) + k];
    const float ws = W_edge[(i * CC + o) * (2 * CC) + CC + k];
    g_wt[((i * 2 + 0) * CC + k) * CC + o] = wd;
    g_wt[((i * 2 + 1) * CC + k) * CC + o] = ws - wd;
}

// acc[op*4+p] = {y[o0+2op], y[o0+2op+1]} at pixel px0+p.
// Per k: 1 weight LDS.128 (o-pairs, 1 wf) + 2 dup-x LDS.128 (1 wf each) + 8 FFMA2.
#define K_BODY(ACC, WROW, XROW)                                               \
  _Pragma("unroll 8")                                                         \
  for (int k = 0; k < 32; ++k) {                                              \
      const ulonglong2 w  = *(const ulonglong2*)((WROW) + k * CC + o0);       \
      const ulonglong2 xa = *(const ulonglong2*)((XROW) + k * XDS + 2 * px0); \
      const ulonglong2 xb = *(const ulonglong2*)((XROW) + k * XDS + 2 * px0 + 4); \
      (ACC)[0] = fma2(w.x, xa.x, (ACC)[0]);                                   \
      (ACC)[1] = fma2(w.x, xa.y, (ACC)[1]);                                   \
      (ACC)[2] = fma2(w.x, xb.x, (ACC)[2]);                                   \
      (ACC)[3] = fma2(w.x, xb.y, (ACC)[3]);                                   \
      (ACC)[4] = fma2(w.y, xa.x, (ACC)[4]);                                   \
      (ACC)[5] = fma2(w.y, xa.y, (ACC)[5]);                                   \
      (ACC)[6] = fma2(w.y, xb.x, (ACC)[6]);                                   \
      (ACC)[7] = fma2(w.y, xb.y, (ACC)[7]);                                   \
  }

// out[i] = x_i + sum_{j!=i} relu(Wd_i @ x_j + C_i) * x_j
// C_i = (Ws_i - Wd_i) @ x_i + b_i
extern "C" __global__ void __launch_bounds__(256, 2)
step_kernel(const float* __restrict__ in,
            const float* __restrict__ b_edge,   // [8][32]
            float* __restrict__ out)
{
    extern __shared__ float sm[];
    float* xd = sm;                    // [n*32+k][XDS]: {x,x} dup pairs (32 px -> 32 fl + pad... 16 px -> 32 dup fl)
    float* wd = sm + XD_F;             // [i*32+k][32 o]
    float* xt = sm + XD_F + WD_F;      // [n*16+px][XDS]: c fastest

    const int bx    = blockIdx.x;
    const int b     = bx / NTILE;
    const int pbase = (bx % NTILE) * PT;
    const int tid   = threadIdx.x;

    // ---- x tile: 1024 float4, 4/thread; write dup + transposed copies ----
    #pragma unroll
    for (int t = 0; t < 4; ++t) {
        const int e   = tid + t * 256;   // 0..1023
        const int row = e >> 2;          // n*32 + k
        const int c4  = e & 3;
        const int n = row >> 5, k = row & 31;
        const float4 v = *reinterpret_cast<const float4*>(
            in + ((n * BB + b) * CC + k) * HW + pbase + c4 * 4);
        float* dr = xd + row * XDS + c4 * 8;
        float4 d0; d0.x = v.x; d0.y = v.x; d0.z = v.y; d0.w = v.y;
        float4 d1; d1.x = v.z; d1.y = v.z; d1.z = v.w; d1.w = v.w;
        *reinterpret_cast<float4*>(dr)     = d0;
        *reinterpret_cast<float4*>(dr + 4) = d1;
        float* tb = xt + n * PT * XDS + k;
        tb[(c4 * 4 + 0) * XDS] = v.x;
        tb[(c4 * 4 + 1) * XDS] = v.y;
        tb[(c4 * 4 + 2) * XDS] = v.z;
        tb[(c4 * 4 + 3) * XDS] = v.w;
    }
    // ---- Wd stage: 2048 float4, 8/thread (g_wt is L2-resident) ----
    #pragma unroll
    for (int t = 0; t < 8; ++t) {
        const int e   = tid + t * 256;   // 0..2047
        const int row = e >> 3;          // i*32 + k
        const int o4  = e & 7;
        const int i2 = row >> 5, k = row & 31;
        const float4 v = *reinterpret_cast<const float4*>(
            g_wt + ((i2 * 2 + 0) * CC + k) * CC + o4 * 4);
        *reinterpret_cast<float4*>(wd + row * CC + o4 * 4) = v;
    }
    __syncthreads();   // the only block-wide sync

    const int i    = tid >> 5;          // warp = receiver
    const int lane = tid & 31;
    const int rg   = lane >> 2;         // 8 o-groups
    const int pg   = lane & 3;          // 4 px-groups
    const int o0   = rg * 4;
    const int px0  = pg * 4;

    const float* wdi = wd + i * (CC * CC);
    const float* xdi = xd + i * CC * XDS;
    const float* xti = xt + i * PT * XDS;

    // ---- C-GEMM: C_i = Wc_i @ x_i + b_i (Wc streamed from L2) ----
    ull accC[8];
    {
        const float4 bv = __ldg(reinterpret_cast<const float4*>(b_edge + i * CC + o0));
        const ull b0 = pack2(bv.x, bv.y), b1 = pack2(bv.z, bv.w);
        #pragma unroll
        for (int p = 0; p < 4; ++p) { accC[p] = b0; accC[4 + p] = b1; }
        const float* wcg = g_wt + ((i * 2 + 1) * CC) * CC;
        K_BODY(accC, wcg, xdi)
    }

    // ---- residual init from transposed copy ----
    float accO[4][4];
    #pragma unroll
    for (int p = 0; p < 4; ++p) {
        const float4 v = *reinterpret_cast<const float4*>(
            xti + (px0 + p) * XDS + o0);
        accO[0][p] = v.x; accO[1][p] = v.y; accO[2][p] = v.z; accO[3][p] = v.w;
    }

    // ---- j-loop ----
    #pragma unroll 1
    for (int jl = 0; jl < 7; ++jl) {
        const int jj = jl + (jl >= i ? 1 : 0);
        ull accY[8];
        #pragma unroll
        for (int q = 0; q < 8; ++q) accY[q] = accC[q];

        K_BODY(accY, wdi, xd + jj * CC * XDS)

        // epilogue: accO += relu(Y) * x_j (one float4 per pixel covers 4 o's)
        const float* xtj = xt + jj * PT * XDS;
        #pragma unroll
        for (int p = 0; p < 4; ++p) {
            const float4 xv = *reinterpret_cast<const float4*>(
                xtj + (px0 + p) * XDS + o0);
            U2 y0; y0.u = accY[p];
            U2 y1; y1.u = accY[4 + p];
            accO[0][p] = fmaf(fmaxf(y0.f.x, 0.0f), xv.x, accO[0][p]);
            accO[1][p] = fmaf(fmaxf(y0.f.y, 0.0f), xv.y, accO[1][p]);
            accO[2][p] = fmaf(fmaxf(y1.f.x, 0.0f), xv.z, accO[2][p]);
            accO[3][p] = fmaf(fmaxf(y1.f.y, 0.0f), xv.w, accO[3][p]);
        }
    }

    // ---- store: 4 channel rows x float4 ----
    #pragma unroll
    for (int n = 0; n < 4; ++n) {
        float4 v;
        v.x = accO[n][0]; v.y = accO[n][1]; v.z = accO[n][2]; v.w = accO[n][3];
        *reinterpret_cast<float4*>(
            out + ((i * BB + b) * CC + (o0 + n)) * HW + pbase + px0) = v;
    }
}

extern "C" void kernel_launch(void* const* d_in, const int* in_sizes, int n_in,
                              void* d_out, int out_size) {
    const float* nodes = (const float*)d_in[0];
    const float* W     = (const float*)d_in[1];
    const float* bvec  = (const float*)d_in[2];
    float* out         = (float*)d_out;

    float *buf0 = nullptr, *buf1 = nullptr;
    cudaGetSymbolAddress((void**)&buf0, g_buf0);
    cudaGetSymbolAddress((void**)&buf1, g_buf1);

    cudaFuncSetAttribute(step_kernel,
                         cudaFuncAttributeMaxDynamicSharedMemorySize, SMEM_BYTES);

    prep_kernel<<<32, 256>>>(W);

    const dim3 grid(BB * NTILE);   // 2304 blocks
    const dim3 block(256);
    step_kernel<<<grid, block, SMEM_BYTES>>>(nodes, bvec, buf0);
    step_kernel<<<grid, block, SMEM_BYTES>>>(buf0,  bvec, buf1);
    step_kernel<<<grid, block, SMEM_BYTES>>>(buf1,  bvec, out);
}